// round 1
// baseline (speedup 1.0000x reference)
#include <cuda_runtime.h>
#include <cuda_bf16.h>
#include <math.h>

// Problem constants
#define BSZ 4096
#define U   1024
#define FOURU 4096
#define M   20
#define OUT_ROW 1086           // o(1024) + pi(20) + mux(20) + muy(20) + xp + yp
#define NS_ROW  1026           // h(1024) + xp + yp
#define OUT_NS_OFF (BSZ * OUT_ROW)
#define STATES_ROW 1026        // U + 2

// Scratch (device globals: allowed; no runtime allocation)
__device__ float g_z[BSZ * U];
__device__ float g_r[BSZ * U];
__device__ float g_h[BSZ * U];

// ---------------------------------------------------------------------------
// Fused GEMM chain kernel. MODE:
//   1: zr = h @ R[:, 0:2048]      -> z = sigmoid (cols <1024), r = sigmoid
//   2: hh = (r*h) @ R[:, 2048:3072] -> h_new = z*h + (1-z)*tanh(...), write h
//   3: o  = h_new @ R[:, 3072:4096] -> o = tanh(...), write to out
// Tile: BM=128, BN=64, BK=16, 256 threads, 8x4 micro-tile per thread.
// ---------------------------------------------------------------------------
template<int MODE>
__global__ __launch_bounds__(256)
void gemm_fused(const float* __restrict__ states,
                const int*   __restrict__ inp,
                const float* __restrict__ R,
                const float* __restrict__ kernel_c,
                const float* __restrict__ bias_z,
                const float* __restrict__ bias,
                const float* __restrict__ kernel_d,
                float* __restrict__ out)
{
    constexpr int BM = 128, BN = 64, BK = 16, TM = 8, TN = 4;
    __shared__ float As[BK][BM + 8];   // +8 pad: keeps 8-float rows 32B aligned
    __shared__ float Bs[BK][BN];
    __shared__ int   ch_s[BM];
    __shared__ float d0_s[BM], d1_s[BM];

    const int tid = threadIdx.x;
    const int tx  = tid & 15;          // col group
    const int ty  = tid >> 4;          // row group
    const int rowBase = blockIdx.y * BM;
    const int colBase = blockIdx.x * BN;                 // stage-local col
    const int stageOff = (MODE == 1) ? 0 : (MODE == 2 ? 2048 : 3072);
    const int rcol = stageOff + colBase;                 // col in R / pre space

    // Per-row metadata for the epilogue
    for (int i = tid; i < BM; i += 256) {
        int b   = rowBase + i;
        ch_s[i] = inp[b];
        d0_s[i] = states[b * STATES_ROW + U];
        d1_s[i] = states[b * STATES_ROW + U + 1];
    }

    float acc[TM][TN];
    #pragma unroll
    for (int i = 0; i < TM; i++)
        #pragma unroll
        for (int j = 0; j < TN; j++) acc[i][j] = 0.0f;

    const int aC = tid & 15;       // k within tile
    const int aR = tid >> 4;       // base row (stride 16)

    for (int k0 = 0; k0 < U; k0 += BK) {
        // Load A tile (transposed into smem)
        #pragma unroll
        for (int i = 0; i < 8; i++) {
            int r  = aR + i * 16;
            int gb = rowBase + r;
            int gk = k0 + aC;
            float v;
            if (MODE == 1)      v = states[gb * STATES_ROW + gk];
            else if (MODE == 2) v = g_r[gb * U + gk] * states[gb * STATES_ROW + gk];
            else                v = g_h[gb * U + gk];
            As[aC][r] = v;
        }
        // Load B tile (16x64) as float4, R row stride = 4096 floats (16B aligned)
        {
            int kk = tid >> 4;
            int n  = (tid & 15) * 4;
            const float4 v = *reinterpret_cast<const float4*>(
                &R[(size_t)(k0 + kk) * FOURU + rcol + n]);
            *reinterpret_cast<float4*>(&Bs[kk][n]) = v;
        }
        __syncthreads();

        #pragma unroll
        for (int kk = 0; kk < BK; kk++) {
            float a[TM], b[TN];
            const float4 a0 = *reinterpret_cast<const float4*>(&As[kk][ty * TM]);
            const float4 a1 = *reinterpret_cast<const float4*>(&As[kk][ty * TM + 4]);
            a[0]=a0.x; a[1]=a0.y; a[2]=a0.z; a[3]=a0.w;
            a[4]=a1.x; a[5]=a1.y; a[6]=a1.z; a[7]=a1.w;
            const float4 b0 = *reinterpret_cast<const float4*>(&Bs[kk][tx * TN]);
            b[0]=b0.x; b[1]=b0.y; b[2]=b0.z; b[3]=b0.w;
            #pragma unroll
            for (int i = 0; i < TM; i++)
                #pragma unroll
                for (int j = 0; j < TN; j++)
                    acc[i][j] = fmaf(a[i], b[j], acc[i][j]);
        }
        __syncthreads();
    }

    // Fused epilogue
    #pragma unroll
    for (int i = 0; i < TM; i++) {
        const int r = ty * TM + i;
        const int b = rowBase + r;
        const int ch = ch_s[r];
        const float d0 = d0_s[r], d1 = d1_s[r];
        const int pc = rcol + tx * TN;         // pre-space col (16B aligned)
        const float4 kc  = *reinterpret_cast<const float4*>(&kernel_c[(size_t)ch * FOURU + pc]);
        const float4 kd0 = *reinterpret_cast<const float4*>(&kernel_d[pc]);
        const float4 kd1 = *reinterpret_cast<const float4*>(&kernel_d[FOURU + pc]);
        const float kcv[4]  = {kc.x, kc.y, kc.z, kc.w};
        const float kd0v[4] = {kd0.x, kd0.y, kd0.z, kd0.w};
        const float kd1v[4] = {kd1.x, kd1.y, kd1.z, kd1.w};
        #pragma unroll
        for (int j = 0; j < TN; j++) {
            const int n = colBase + tx * TN + j;   // stage-local col
            float v = acc[i][j] + kcv[j] + d0 * kd0v[j] + d1 * kd1v[j];
            if (MODE == 1) {
                if (n < U) {
                    v += bias_z[n];
                    g_z[(size_t)b * U + n] = 1.0f / (1.0f + expf(-v));
                } else {
                    v += bias[n - U];
                    g_r[(size_t)b * U + (n - U)] = 1.0f / (1.0f + expf(-v));
                }
            } else if (MODE == 2) {
                v += bias[U + n];
                const float hh   = tanhf(v);
                const float z    = g_z[(size_t)b * U + n];
                const float hold = states[b * STATES_ROW + n];
                const float h    = z * hold + (1.0f - z) * hh;
                g_h[(size_t)b * U + n] = h;
                out[OUT_NS_OFF + (size_t)b * NS_ROW + n] = h;
            } else {
                v += bias[2 * U + n];
                out[(size_t)b * OUT_ROW + n] = tanhf(v);
            }
        }
    }
}

// ---------------------------------------------------------------------------
// GMM head: gmm = o @ Wgmm + bgmm ; softmax(pi over 20) ; x/y preds.
// 128 rows per block, 64 (60 used) cols, K=1024.
// ---------------------------------------------------------------------------
__global__ __launch_bounds__(256)
void gmm_kernel(const float* __restrict__ W,     // (1024, 60)
                const float* __restrict__ bg,    // (60,)
                float* __restrict__ out)
{
    constexpr int BM = 128, BN = 64, BK = 16, TM = 8, TN = 4;
    __shared__ float As[BK][BM + 8];
    __shared__ float Ws[BK][BN];
    __shared__ float Gm[BM][BN + 1];   // padded: conflict-free row reads

    const int tid = threadIdx.x;
    const int tx  = tid & 15;
    const int ty  = tid >> 4;
    const int rowBase = blockIdx.x * BM;

    float acc[TM][TN];
    #pragma unroll
    for (int i = 0; i < TM; i++)
        #pragma unroll
        for (int j = 0; j < TN; j++) acc[i][j] = 0.0f;

    const int aC = tid & 15;
    const int aR = tid >> 4;

    for (int k0 = 0; k0 < U; k0 += BK) {
        #pragma unroll
        for (int i = 0; i < 8; i++) {
            int r  = aR + i * 16;
            int gb = rowBase + r;
            // o lives in the already-written output buffer
            As[aC][r] = out[(size_t)gb * OUT_ROW + k0 + aC];
        }
        {
            int kk = tid >> 4;
            int n  = (tid & 15) * 4;
            #pragma unroll
            for (int jj = 0; jj < 4; jj++) {
                int c = n + jj;
                Ws[kk][c] = (c < 60) ? W[(size_t)(k0 + kk) * 60 + c] : 0.0f;
            }
        }
        __syncthreads();
        #pragma unroll
        for (int kk = 0; kk < BK; kk++) {
            float a[TM], b[TN];
            const float4 a0 = *reinterpret_cast<const float4*>(&As[kk][ty * TM]);
            const float4 a1 = *reinterpret_cast<const float4*>(&As[kk][ty * TM + 4]);
            a[0]=a0.x; a[1]=a0.y; a[2]=a0.z; a[3]=a0.w;
            a[4]=a1.x; a[5]=a1.y; a[6]=a1.z; a[7]=a1.w;
            const float4 b0 = *reinterpret_cast<const float4*>(&Ws[kk][tx * TN]);
            b[0]=b0.x; b[1]=b0.y; b[2]=b0.z; b[3]=b0.w;
            #pragma unroll
            for (int i = 0; i < TM; i++)
                #pragma unroll
                for (int j = 0; j < TN; j++)
                    acc[i][j] = fmaf(a[i], b[j], acc[i][j]);
        }
        __syncthreads();
    }

    // Stage gmm (+bias) into smem
    #pragma unroll
    for (int i = 0; i < TM; i++) {
        #pragma unroll
        for (int j = 0; j < TN; j++) {
            int c = tx * TN + j;
            float bv = (c < 60) ? bg[c] : 0.0f;
            Gm[ty * TM + i][c] = acc[i][j] + bv;
        }
    }
    __syncthreads();

    // Per-row softmax + predictions (threads 0..127, one row each)
    if (tid < BM) {
        const int b = rowBase + tid;
        float e[M];
        float s = 0.0f;
        #pragma unroll
        for (int j = 0; j < M; j++) {
            float ev = expf(Gm[tid][j]);
            ev = fminf(fmaxf(ev, 1e-10f), 1e10f);
            e[j] = ev;
            s += ev;
        }
        const float inv = 1.0f / s;
        float xp = 0.0f, yp = 0.0f;
        const size_t base = (size_t)b * OUT_ROW + U;
        #pragma unroll
        for (int j = 0; j < M; j++) {
            const float pi = e[j] * inv;
            const float mx = Gm[tid][M + j];
            const float my = Gm[tid][2 * M + j];
            out[base + j]         = pi;
            out[base + M + j]     = mx;
            out[base + 2 * M + j] = my;
            xp = fmaf(pi, mx, xp);
            yp = fmaf(pi, my, yp);
        }
        out[base + 3 * M]     = xp;
        out[base + 3 * M + 1] = yp;
        out[OUT_NS_OFF + (size_t)b * NS_ROW + U]     = xp;
        out[OUT_NS_OFF + (size_t)b * NS_ROW + U + 1] = yp;
    }
}

extern "C" void kernel_launch(void* const* d_in, const int* in_sizes, int n_in,
                              void* d_out, int out_size)
{
    const int*   inp      = (const int*)  d_in[0];   // (B,1) int32
    const float* states   = (const float*)d_in[1];   // (B, U+2)
    const float* bias_z   = (const float*)d_in[2];   // (U,)
    const float* R        = (const float*)d_in[3];   // (U, 4U)
    const float* kernel_c = (const float*)d_in[4];   // (C, 4U)
    const float* bias     = (const float*)d_in[5];   // (3U,)
    const float* kernel_d = (const float*)d_in[6];   // (2, 4U)
    const float* Wgmm     = (const float*)d_in[7];   // (U, 3M)
    const float* bgmm     = (const float*)d_in[8];   // (3M,)
    float* out = (float*)d_out;

    dim3 blk(256);
    // Stage 1: zr (N = 2048)
    gemm_fused<1><<<dim3(2048 / 64, BSZ / 128), blk>>>(states, inp, R, kernel_c,
                                                       bias_z, bias, kernel_d, out);
    // Stage 2: hh + GRU blend (N = 1024)
    gemm_fused<2><<<dim3(1024 / 64, BSZ / 128), blk>>>(states, inp, R, kernel_c,
                                                       bias_z, bias, kernel_d, out);
    // Stage 3: o (N = 1024)
    gemm_fused<3><<<dim3(1024 / 64, BSZ / 128), blk>>>(states, inp, R, kernel_c,
                                                       bias_z, bias, kernel_d, out);
    // Stage 4: GMM head + softmax + preds
    gmm_kernel<<<BSZ / 128, blk>>>(Wgmm, bgmm, out);
}

// round 2
// speedup vs baseline: 1.0816x; 1.0816x over previous
#include <cuda_runtime.h>
#include <cuda_bf16.h>
#include <math.h>

// Problem constants
#define BSZ 4096
#define U   1024
#define FOURU 4096
#define M   20
#define OUT_ROW 1086           // o(1024) + pi(20) + mux(20) + muy(20) + xp + yp
#define NS_ROW  1026           // h(1024) + xp + yp
#define OUT_NS_OFF (BSZ * OUT_ROW)
#define STATES_ROW 1026        // U + 2

typedef unsigned long long ull;

// Packed fp32x2 FMA (SASS FFMA2) — 2 fp32 FMAs per fma-pipe slot.
#define FMA2(d, a, b) \
    asm("fma.rn.f32x2 %0, %1, %2, %3;" : "=l"(d) : "l"(a), "l"(b), "l"(d))
// Duplicate one float into both halves of a 64-bit pair.
#define PACKDUP(d, x) \
    asm("mov.b64 %0, {%1, %1};" : "=l"(d) : "f"(x))
#define UNPACK2(lo, hi, v) \
    asm("mov.b64 {%0, %1}, %2;" : "=f"(lo), "=f"(hi) : "l"(v))

// Scratch (device globals: allowed; no runtime allocation)
__device__ float g_z[BSZ * U];
__device__ float g_r[BSZ * U];
__device__ float g_h[BSZ * U];

// ---------------------------------------------------------------------------
// Fused GEMM chain kernel using packed f32x2 FMAs.
//   MODE 1: zr = h @ R[:, 0:2048]        -> z, r = sigmoid
//   MODE 2: hh = (r*h) @ R[:, 2048:3072] -> h = z*h_old + (1-z)*tanh(...)
//   MODE 3: o  = h @ R[:, 3072:4096]     -> o = tanh(...)
// Tile: BM=128, BN=128, BK=16, 256 threads, 8x8 micro-tile (32 f32x2 accs).
// ---------------------------------------------------------------------------
template<int MODE>
__global__ __launch_bounds__(256, 2)
void gemm_fused(const float* __restrict__ states,
                const int*   __restrict__ inp,
                const float* __restrict__ R,
                const float* __restrict__ kernel_c,
                const float* __restrict__ bias_z,
                const float* __restrict__ bias,
                const float* __restrict__ kernel_d,
                float* __restrict__ out)
{
    constexpr int BM = 128, BN = 128, BK = 16;
    __shared__ float As[BK][BM + 8];   // row stride 136 floats (16B aligned)
    __shared__ float Bs[BK][BN];
    __shared__ int   ch_s[BM];
    __shared__ float d0_s[BM], d1_s[BM];

    const int tid = threadIdx.x;
    const int tx  = tid & 15;          // 16 col groups * 8 cols
    const int ty  = tid >> 4;          // 16 row groups * 8 rows
    const int rowBase = blockIdx.y * BM;
    const int colBase = blockIdx.x * BN;                 // stage-local col
    const int stageOff = (MODE == 1) ? 0 : (MODE == 2 ? 2048 : 3072);
    const int rcol = stageOff + colBase;                 // col in R / pre space

    for (int i = tid; i < BM; i += 256) {
        int b   = rowBase + i;
        ch_s[i] = inp[b];
        d0_s[i] = states[b * STATES_ROW + U];
        d1_s[i] = states[b * STATES_ROW + U + 1];
    }

    ull acc[8][4];                     // acc[i][j]: row ty*8+i, cols tx*8+2j..+1
    #pragma unroll
    for (int i = 0; i < 8; i++)
        #pragma unroll
        for (int j = 0; j < 4; j++) acc[i][j] = 0ull;

    const int aC = tid & 15;           // k within tile
    const int aR = tid >> 4;           // base row (stride 16)

    for (int k0 = 0; k0 < U; k0 += BK) {
        // Load A tile (transposed into smem): 16x128
        #pragma unroll
        for (int i = 0; i < 8; i++) {
            int r  = aR + i * 16;
            int gb = rowBase + r;
            int gk = k0 + aC;
            float v;
            if (MODE == 1)      v = states[gb * STATES_ROW + gk];
            else if (MODE == 2) v = g_r[(size_t)gb * U + gk] * states[gb * STATES_ROW + gk];
            else                v = g_h[(size_t)gb * U + gk];
            As[aC][r] = v;
        }
        // Load B tile (16x128) as float4; R row stride = 4096 floats
        #pragma unroll
        for (int p = 0; p < 2; p++) {
            int idx = tid + p * 256;           // 0..511
            int kk  = idx >> 5;
            int n   = (idx & 31) * 4;
            const float4 v = *reinterpret_cast<const float4*>(
                &R[(size_t)(k0 + kk) * FOURU + rcol + n]);
            *reinterpret_cast<float4*>(&Bs[kk][n]) = v;
        }
        __syncthreads();

        #pragma unroll
        for (int kk = 0; kk < BK; kk++) {
            // A: 8 values, duplicated into f32x2 pairs
            const float4 a0 = *reinterpret_cast<const float4*>(&As[kk][ty * 8]);
            const float4 a1 = *reinterpret_cast<const float4*>(&As[kk][ty * 8 + 4]);
            ull A2[8];
            PACKDUP(A2[0], a0.x); PACKDUP(A2[1], a0.y);
            PACKDUP(A2[2], a0.z); PACKDUP(A2[3], a0.w);
            PACKDUP(A2[4], a1.x); PACKDUP(A2[5], a1.y);
            PACKDUP(A2[6], a1.z); PACKDUP(A2[7], a1.w);
            // B: 8 values = 4 naturally-packed f32x2 pairs
            const ulonglong2 b0 = *reinterpret_cast<const ulonglong2*>(&Bs[kk][tx * 8]);
            const ulonglong2 b1 = *reinterpret_cast<const ulonglong2*>(&Bs[kk][tx * 8 + 4]);
            const ull B2[4] = {b0.x, b0.y, b1.x, b1.y};
            #pragma unroll
            for (int i = 0; i < 8; i++)
                #pragma unroll
                for (int j = 0; j < 4; j++)
                    FMA2(acc[i][j], A2[i], B2[j]);
        }
        __syncthreads();
    }

    // Fused epilogue
    #pragma unroll
    for (int i = 0; i < 8; i++) {
        const int r = ty * 8 + i;
        const int b = rowBase + r;
        const int ch = ch_s[r];
        const float d0 = d0_s[r], d1 = d1_s[r];
        const int pc = rcol + tx * 8;          // pre-space col (16B aligned)
        float kcv[8], kd0v[8], kd1v[8];
        #pragma unroll
        for (int q = 0; q < 2; q++) {
            const float4 kc  = *reinterpret_cast<const float4*>(&kernel_c[(size_t)ch * FOURU + pc + q * 4]);
            const float4 kd0 = *reinterpret_cast<const float4*>(&kernel_d[pc + q * 4]);
            const float4 kd1 = *reinterpret_cast<const float4*>(&kernel_d[FOURU + pc + q * 4]);
            kcv[q*4+0]=kc.x;  kcv[q*4+1]=kc.y;  kcv[q*4+2]=kc.z;  kcv[q*4+3]=kc.w;
            kd0v[q*4+0]=kd0.x;kd0v[q*4+1]=kd0.y;kd0v[q*4+2]=kd0.z;kd0v[q*4+3]=kd0.w;
            kd1v[q*4+0]=kd1.x;kd1v[q*4+1]=kd1.y;kd1v[q*4+2]=kd1.z;kd1v[q*4+3]=kd1.w;
        }
        float av[8];
        #pragma unroll
        for (int j = 0; j < 4; j++) UNPACK2(av[2*j], av[2*j+1], acc[i][j]);
        #pragma unroll
        for (int j = 0; j < 8; j++) {
            const int n = colBase + tx * 8 + j;    // stage-local col
            float v = av[j] + kcv[j] + d0 * kd0v[j] + d1 * kd1v[j];
            if (MODE == 1) {
                if (n < U) {
                    v += bias_z[n];
                    g_z[(size_t)b * U + n] = 1.0f / (1.0f + expf(-v));
                } else {
                    v += bias[n - U];
                    g_r[(size_t)b * U + (n - U)] = 1.0f / (1.0f + expf(-v));
                }
            } else if (MODE == 2) {
                v += bias[U + n];
                const float hh   = tanhf(v);
                const float z    = g_z[(size_t)b * U + n];
                const float hold = states[b * STATES_ROW + n];
                const float h    = z * hold + (1.0f - z) * hh;
                g_h[(size_t)b * U + n] = h;
                out[OUT_NS_OFF + (size_t)b * NS_ROW + n] = h;
            } else {
                v += bias[2 * U + n];
                out[(size_t)b * OUT_ROW + n] = tanhf(v);
            }
        }
    }
}

// ---------------------------------------------------------------------------
// GMM head: gmm = o @ Wgmm + bgmm ; softmax(pi over 20) ; x/y preds.
// BM=32 rows per block (128 CTAs -> fills the chip), 64 (60 used) cols.
// ---------------------------------------------------------------------------
__global__ __launch_bounds__(256)
void gmm_kernel(const float* __restrict__ W,     // (1024, 60)
                const float* __restrict__ bg,    // (60,)
                float* __restrict__ out)
{
    constexpr int BM = 32, BN = 64, BK = 16, TM = 2, TN = 4;
    __shared__ float As[BK][BM + 4];
    __shared__ float Ws[BK][BN];
    __shared__ float Gm[BM][BN + 1];

    const int tid = threadIdx.x;
    const int tx  = tid & 15;          // 16 * 4 = 64 cols
    const int ty  = tid >> 4;          // 16 * 2 = 32 rows
    const int rowBase = blockIdx.x * BM;

    float acc[TM][TN];
    #pragma unroll
    for (int i = 0; i < TM; i++)
        #pragma unroll
        for (int j = 0; j < TN; j++) acc[i][j] = 0.0f;

    for (int k0 = 0; k0 < U; k0 += BK) {
        // A tile 16x32: 512 elems, 2 per thread; consecutive tid -> consecutive k
        #pragma unroll
        for (int p = 0; p < 2; p++) {
            int idx = tid + p * 256;
            int kk  = idx & 15;
            int r   = idx >> 4;
            As[kk][r] = out[(size_t)(rowBase + r) * OUT_ROW + k0 + kk];
        }
        // W tile 16x64 (60 real cols)
        {
            int kk = tid >> 4;
            int n  = (tid & 15) * 4;
            #pragma unroll
            for (int jj = 0; jj < 4; jj++) {
                int c = n + jj;
                Ws[kk][c] = (c < 60) ? W[(size_t)(k0 + kk) * 60 + c] : 0.0f;
            }
        }
        __syncthreads();
        #pragma unroll
        for (int kk = 0; kk < BK; kk++) {
            float a[TM], b[TN];
            a[0] = As[kk][ty * TM];
            a[1] = As[kk][ty * TM + 1];
            const float4 b0 = *reinterpret_cast<const float4*>(&Ws[kk][tx * TN]);
            b[0]=b0.x; b[1]=b0.y; b[2]=b0.z; b[3]=b0.w;
            #pragma unroll
            for (int i = 0; i < TM; i++)
                #pragma unroll
                for (int j = 0; j < TN; j++)
                    acc[i][j] = fmaf(a[i], b[j], acc[i][j]);
        }
        __syncthreads();
    }

    #pragma unroll
    for (int i = 0; i < TM; i++)
        #pragma unroll
        for (int j = 0; j < TN; j++) {
            int c = tx * TN + j;
            float bv = (c < 60) ? bg[c] : 0.0f;
            Gm[ty * TM + i][c] = acc[i][j] + bv;
        }
    __syncthreads();

    if (tid < BM) {
        const int b = rowBase + tid;
        float e[M];
        float s = 0.0f;
        #pragma unroll
        for (int j = 0; j < M; j++) {
            float ev = expf(Gm[tid][j]);
            ev = fminf(fmaxf(ev, 1e-10f), 1e10f);
            e[j] = ev;
            s += ev;
        }
        const float inv = 1.0f / s;
        float xp = 0.0f, yp = 0.0f;
        const size_t base = (size_t)b * OUT_ROW + U;
        #pragma unroll
        for (int j = 0; j < M; j++) {
            const float pi = e[j] * inv;
            const float mx = Gm[tid][M + j];
            const float my = Gm[tid][2 * M + j];
            out[base + j]         = pi;
            out[base + M + j]     = mx;
            out[base + 2 * M + j] = my;
            xp = fmaf(pi, mx, xp);
            yp = fmaf(pi, my, yp);
        }
        out[base + 3 * M]     = xp;
        out[base + 3 * M + 1] = yp;
        out[OUT_NS_OFF + (size_t)b * NS_ROW + U]     = xp;
        out[OUT_NS_OFF + (size_t)b * NS_ROW + U + 1] = yp;
    }
}

extern "C" void kernel_launch(void* const* d_in, const int* in_sizes, int n_in,
                              void* d_out, int out_size)
{
    const int*   inp      = (const int*)  d_in[0];   // (B,1) int32
    const float* states   = (const float*)d_in[1];   // (B, U+2)
    const float* bias_z   = (const float*)d_in[2];   // (U,)
    const float* R        = (const float*)d_in[3];   // (U, 4U)
    const float* kernel_c = (const float*)d_in[4];   // (C, 4U)
    const float* bias     = (const float*)d_in[5];   // (3U,)
    const float* kernel_d = (const float*)d_in[6];   // (2, 4U)
    const float* Wgmm     = (const float*)d_in[7];   // (U, 3M)
    const float* bgmm     = (const float*)d_in[8];   // (3M,)
    float* out = (float*)d_out;

    dim3 blk(256);
    // Stage 1: zr (N = 2048)
    gemm_fused<1><<<dim3(2048 / 128, BSZ / 128), blk>>>(states, inp, R, kernel_c,
                                                        bias_z, bias, kernel_d, out);
    // Stage 2: hh + GRU blend (N = 1024)
    gemm_fused<2><<<dim3(1024 / 128, BSZ / 128), blk>>>(states, inp, R, kernel_c,
                                                        bias_z, bias, kernel_d, out);
    // Stage 3: o (N = 1024)
    gemm_fused<3><<<dim3(1024 / 128, BSZ / 128), blk>>>(states, inp, R, kernel_c,
                                                        bias_z, bias, kernel_d, out);
    // Stage 4: GMM head + softmax + preds
    gmm_kernel<<<BSZ / 32, blk>>>(Wgmm, bgmm, out);
}

// round 4
// speedup vs baseline: 2.3459x; 2.1688x over previous
#include <cuda_runtime.h>
#include <cuda_bf16.h>
#include <math.h>
#include <stdint.h>

// ---------------------------------------------------------------- constants
#define BSZ 4096
#define U   1024
#define FOURU 4096
#define M   20
#define OUT_ROW 1086
#define NS_ROW  1026
#define OUT_NS_OFF (BSZ * OUT_ROW)
#define STATES_ROW 1026

// stage GEMM tiling
#define BM 128
#define BN 128
#define BK 32
#define NK (U / BK)          // 32 k-iterations
#define ROWH 40              // smem row stride in halves (32 + 8 pad) = 80B
#define ARR_BYTES (BM * ROWH * 2)      // 10240 B per tile array
#define BUF_BYTES (4 * ARR_BYTES)      // Ahi, Alo, Bhi, Blo
#define EPI_OFF   (2 * BUF_BYTES)
#define SMEM_BYTES (EPI_OFF + 6 * 512) // + ch/d0/d1/kd0/kd1/bias

// ---------------------------------------------------------------- scratch
__device__ __nv_bfloat16 g_Bhi[4096u * 1024u];   // R^T split, [n, k]
__device__ __nv_bfloat16 g_Blo[4096u * 1024u];
__device__ __nv_bfloat16 g_A1hi[BSZ * U], g_A1lo[BSZ * U];   // h
__device__ __nv_bfloat16 g_A2hi[BSZ * U], g_A2lo[BSZ * U];   // r*h
__device__ __nv_bfloat16 g_A3hi[BSZ * U], g_A3lo[BSZ * U];   // h_new
__device__ float g_z[BSZ * U];
__device__ float g_gmm[BSZ * 64];

// ---------------------------------------------------------------- utils
__device__ __forceinline__ uint32_t smem_u32(const void* p) {
    uint32_t a;
    asm("{ .reg .u64 t; cvta.to.shared.u64 t, %1; cvt.u32.u64 %0, t; }"
        : "=r"(a) : "l"(p));
    return a;
}
#define CP_ASYNC16(dst, src) \
    asm volatile("cp.async.cg.shared.global [%0], [%1], 16;" :: "r"(dst), "l"(src))
#define CP_COMMIT() asm volatile("cp.async.commit_group;")
#define CP_WAIT(n)  asm volatile("cp.async.wait_group %0;" :: "n"(n))

__device__ __forceinline__ void mma16816(float* c, const uint32_t* a, const uint32_t* b) {
    asm volatile(
        "mma.sync.aligned.m16n8k16.row.col.f32.bf16.bf16.f32 "
        "{%0,%1,%2,%3}, {%4,%5,%6,%7}, {%8,%9}, {%0,%1,%2,%3};"
        : "+f"(c[0]), "+f"(c[1]), "+f"(c[2]), "+f"(c[3])
        : "r"(a[0]), "r"(a[1]), "r"(a[2]), "r"(a[3]), "r"(b[0]), "r"(b[1]));
}

__device__ __forceinline__ void bfsplit(float v, __nv_bfloat16& hi, __nv_bfloat16& lo) {
    hi = __float2bfloat16(v);
    lo = __float2bfloat16(v - __bfloat162float(hi));
}

// ---------------------------------------------------------------- prep kernels
__global__ void zero_gmm_kernel() {
    g_gmm[blockIdx.x * 1024 + threadIdx.x] = 0.0f;
}

// Transpose + split R: [k,4096] fp32 -> g_B{hi,lo}[n,1024] bf16
__global__ void prep_B_kernel(const float* __restrict__ R) {
    __shared__ float t[32][33];
    const int n0 = blockIdx.x * 32, k0 = blockIdx.y * 32;
    const int tx = threadIdx.x, ty = threadIdx.y;
    #pragma unroll
    for (int i = 0; i < 4; i++)
        t[ty + i * 8][tx] = R[(size_t)(k0 + ty + i * 8) * FOURU + n0 + tx];
    __syncthreads();
    #pragma unroll
    for (int i = 0; i < 4; i++) {
        const int n = n0 + ty + i * 8, k = k0 + tx;
        __nv_bfloat16 hi, lo;
        bfsplit(t[tx][ty + i * 8], hi, lo);
        g_Bhi[(size_t)n * U + k] = hi;
        g_Blo[(size_t)n * U + k] = lo;
    }
}

// Split h (states[:, :U]) into g_A1
__global__ void prep_A1_kernel(const float* __restrict__ states) {
    const int idx = blockIdx.x * 256 + threadIdx.x;
    const int b = idx >> 10, k = idx & 1023;
    __nv_bfloat16 hi, lo;
    bfsplit(states[(size_t)b * STATES_ROW + k], hi, lo);
    g_A1hi[idx] = hi;
    g_A1lo[idx] = lo;
}

// ---------------------------------------------------------------- stage GEMM
// MODE 1: zr = h@R[:,0:2048]  (z for bx<8, r for bx>=8)
// MODE 2: hh = (r*h)@R[:,2048:3072] -> GRU blend, write h/new_state
// MODE 3: o  = h@R[:,3072:4096]     -> tanh, write out
template<int MODE>
__global__ __launch_bounds__(256, 2)
void stage_mma(const float* __restrict__ states,
               const int*   __restrict__ inp,
               const float* __restrict__ kernel_c,
               const float* __restrict__ bias_z,
               const float* __restrict__ bias,
               const float* __restrict__ kernel_d,
               float* __restrict__ out)
{
    extern __shared__ char smem[];
    const uint32_t sb = smem_u32(smem);

    const int tid  = threadIdx.x;
    const int wid  = tid >> 5;
    const int lane = tid & 31;
    const int wM   = wid >> 2;          // 0..1
    const int wN   = wid & 3;           // 0..3
    const int g    = lane >> 2;         // 0..7
    const int tig  = lane & 3;          // 0..3

    const int rowBase  = blockIdx.y * BM;
    const int bx       = blockIdx.x;
    const int stageOff = (MODE == 1) ? 0 : (MODE == 2 ? 2048 : 3072);
    const int nAbs     = stageOff + bx * BN;       // col base in 4096 pre-space

    const __nv_bfloat16* Ah = (MODE == 1) ? g_A1hi : (MODE == 2 ? g_A2hi : g_A3hi);
    const __nv_bfloat16* Al = (MODE == 1) ? g_A1lo : (MODE == 2 ? g_A2lo : g_A3lo);

    // epilogue smem
    int*   ch_s   = (int*)  (smem + EPI_OFF);
    float* d0_s   = (float*)(smem + EPI_OFF + 512);
    float* d1_s   = (float*)(smem + EPI_OFF + 1024);
    float* kd0_s  = (float*)(smem + EPI_OFF + 1536);
    float* kd1_s  = (float*)(smem + EPI_OFF + 2048);
    float* bias_s = (float*)(smem + EPI_OFF + 2560);
    for (int i = tid; i < BM; i += 256) {
        const int b = rowBase + i;
        ch_s[i] = inp[b];
        d0_s[i] = states[(size_t)b * STATES_ROW + U];
        d1_s[i] = states[(size_t)b * STATES_ROW + U + 1];
        kd0_s[i] = kernel_d[nAbs + i];
        kd1_s[i] = kernel_d[FOURU + nAbs + i];
        const int nsc = bx * BN + i;    // stage-local col
        float bv;
        if (MODE == 1) bv = (nsc < U) ? bias_z[nsc] : bias[nsc - U];
        else if (MODE == 2) bv = bias[U + nsc];
        else bv = bias[2 * U + nsc];
        bias_s[i] = bv;
    }

    // issue async loads for one buffer (4 arrays x 2 chunks of 16B per thread)
    auto issue = [&](int buf, int k0) {
        const uint32_t bbase = sb + buf * BUF_BYTES;
        #pragma unroll
        for (int p = 0; p < 2; p++) {
            const int u = tid + p * 256;       // 0..511
            const int r = u >> 2, c = u & 3;
            const uint32_t d = r * 80 + c * 16;
            const size_t asrc = (size_t)(rowBase + r) * U + k0 + c * 8;
            const size_t bsrc = (size_t)(nAbs + r) * U + k0 + c * 8;
            CP_ASYNC16(bbase + d,                 (const void*)(Ah + asrc));
            CP_ASYNC16(bbase + ARR_BYTES + d,     (const void*)(Al + asrc));
            CP_ASYNC16(bbase + 2 * ARR_BYTES + d, (const void*)(g_Bhi + bsrc));
            CP_ASYNC16(bbase + 3 * ARR_BYTES + d, (const void*)(g_Blo + bsrc));
        }
        CP_COMMIT();
    };

    float acc[4][4][4];
    #pragma unroll
    for (int i = 0; i < 4; i++)
        #pragma unroll
        for (int j = 0; j < 4; j++)
            #pragma unroll
            for (int q = 0; q < 4; q++) acc[i][j][q] = 0.0f;

    issue(0, 0);

    for (int kb = 0; kb < NK; kb++) {
        if (kb + 1 < NK) { issue((kb + 1) & 1, (kb + 1) * BK); CP_WAIT(1); }
        else             { CP_WAIT(0); }
        __syncthreads();

        const char* buf = smem + (kb & 1) * BUF_BYTES;
        const __nv_bfloat16* sAh = (const __nv_bfloat16*)(buf);
        const __nv_bfloat16* sAl = (const __nv_bfloat16*)(buf + ARR_BYTES);
        const __nv_bfloat16* sBh = (const __nv_bfloat16*)(buf + 2 * ARR_BYTES);
        const __nv_bfloat16* sBl = (const __nv_bfloat16*)(buf + 3 * ARR_BYTES);

        #pragma unroll
        for (int s16 = 0; s16 < 2; s16++) {
            const int koff = s16 * 16 + tig * 2;
            uint32_t bh[4][2], bl[4][2];
            #pragma unroll
            for (int nf = 0; nf < 4; nf++) {
                const int off = (wN * 32 + nf * 8 + g) * ROWH + koff;
                bh[nf][0] = *(const uint32_t*)(sBh + off);
                bh[nf][1] = *(const uint32_t*)(sBh + off + 8);
                bl[nf][0] = *(const uint32_t*)(sBl + off);
                bl[nf][1] = *(const uint32_t*)(sBl + off + 8);
            }
            #pragma unroll
            for (int mf = 0; mf < 4; mf++) {
                const int off = (wM * 64 + mf * 16 + g) * ROWH + koff;
                uint32_t ah[4], al[4];
                ah[0] = *(const uint32_t*)(sAh + off);
                ah[1] = *(const uint32_t*)(sAh + off + 8 * ROWH);
                ah[2] = *(const uint32_t*)(sAh + off + 8);
                ah[3] = *(const uint32_t*)(sAh + off + 8 * ROWH + 8);
                al[0] = *(const uint32_t*)(sAl + off);
                al[1] = *(const uint32_t*)(sAl + off + 8 * ROWH);
                al[2] = *(const uint32_t*)(sAl + off + 8);
                al[3] = *(const uint32_t*)(sAl + off + 8 * ROWH + 8);
                #pragma unroll
                for (int nf = 0; nf < 4; nf++) {
                    mma16816(acc[mf][nf], ah, bh[nf]);
                    mma16816(acc[mf][nf], ah, bl[nf]);
                    mma16816(acc[mf][nf], al, bh[nf]);
                }
            }
        }
        __syncthreads();
    }

    // ---------------- fused epilogue
    const bool zHalf = (MODE == 1) && (bx < 8);
    #pragma unroll
    for (int mf = 0; mf < 4; mf++) {
        #pragma unroll
        for (int hh = 0; hh < 2; hh++) {
            const int row = wM * 64 + mf * 16 + g + hh * 8;
            const int b   = rowBase + row;
            const int ch  = ch_s[row];
            const float d0 = d0_s[row], d1 = d1_s[row];
            #pragma unroll
            for (int nf = 0; nf < 4; nf++) {
                const int col = wN * 32 + nf * 8 + tig * 2;   // local col (even)
                const float2 kc = *(const float2*)(kernel_c + (size_t)ch * FOURU + nAbs + col);
                float v0 = acc[mf][nf][hh * 2]     + kc.x + d0 * kd0_s[col]     + d1 * kd1_s[col]     + bias_s[col];
                float v1 = acc[mf][nf][hh * 2 + 1] + kc.y + d0 * kd0_s[col + 1] + d1 * kd1_s[col + 1] + bias_s[col + 1];
                if (MODE == 1) {
                    const float s0 = 1.0f / (1.0f + expf(-v0));
                    const float s1 = 1.0f / (1.0f + expf(-v1));
                    if (zHalf) {
                        const int n = bx * BN + col;
                        *(float2*)&g_z[(size_t)b * U + n] = make_float2(s0, s1);
                    } else {
                        const int n2 = (bx - 8) * BN + col;
                        const float2 hv = *(const float2*)(states + (size_t)b * STATES_ROW + n2);
                        __nv_bfloat16 h0, l0, h1, l1;
                        bfsplit(s0 * hv.x, h0, l0);
                        bfsplit(s1 * hv.y, h1, l1);
                        *(uint32_t*)&g_A2hi[(size_t)b * U + n2] =
                            (uint32_t)__bfloat16_as_ushort(h0) | ((uint32_t)__bfloat16_as_ushort(h1) << 16);
                        *(uint32_t*)&g_A2lo[(size_t)b * U + n2] =
                            (uint32_t)__bfloat16_as_ushort(l0) | ((uint32_t)__bfloat16_as_ushort(l1) << 16);
                    }
                } else if (MODE == 2) {
                    const int n = bx * BN + col;
                    const float2 z2  = *(const float2*)&g_z[(size_t)b * U + n];
                    const float2 ho2 = *(const float2*)(states + (size_t)b * STATES_ROW + n);
                    const float hn0 = z2.x * ho2.x + (1.0f - z2.x) * tanhf(v0);
                    const float hn1 = z2.y * ho2.y + (1.0f - z2.y) * tanhf(v1);
                    *(float2*)&out[OUT_NS_OFF + (size_t)b * NS_ROW + n] = make_float2(hn0, hn1);
                    __nv_bfloat16 h0, l0, h1, l1;
                    bfsplit(hn0, h0, l0);
                    bfsplit(hn1, h1, l1);
                    *(uint32_t*)&g_A3hi[(size_t)b * U + n] =
                        (uint32_t)__bfloat16_as_ushort(h0) | ((uint32_t)__bfloat16_as_ushort(h1) << 16);
                    *(uint32_t*)&g_A3lo[(size_t)b * U + n] =
                        (uint32_t)__bfloat16_as_ushort(l0) | ((uint32_t)__bfloat16_as_ushort(l1) << 16);
                } else {
                    const int n = bx * BN + col;
                    *(float2*)&out[(size_t)b * OUT_ROW + n] = make_float2(tanhf(v0), tanhf(v1));
                }
            }
        }
    }
}

// ---------------------------------------------------------------- GMM head
__global__ __launch_bounds__(256)
void gmm_partial(const float* __restrict__ o_src,   // == out (o in first U cols)
                 const float* __restrict__ W)       // (1024, 60)
{
    __shared__ float As[16][68];
    __shared__ float Ws[16][64];
    const int tid = threadIdx.x;
    const int tx = tid & 15, ty = tid >> 4;
    const int rowBase = blockIdx.x * 64;
    const int kBase   = blockIdx.y * 128;

    float acc[4][4];
    #pragma unroll
    for (int i = 0; i < 4; i++)
        #pragma unroll
        for (int j = 0; j < 4; j++) acc[i][j] = 0.0f;

    for (int k0 = kBase; k0 < kBase + 128; k0 += 16) {
        #pragma unroll
        for (int i = 0; i < 4; i++) {
            const int idx = tid + i * 256;
            const int kk = idx & 15, r = idx >> 4;
            As[kk][r] = o_src[(size_t)(rowBase + r) * OUT_ROW + k0 + kk];
        }
        #pragma unroll
        for (int i = 0; i < 4; i++) {
            const int idx = tid + i * 256;
            const int c = idx & 63, kk = idx >> 6;
            Ws[kk][c] = (c < 60) ? W[(size_t)(k0 + kk) * 60 + c] : 0.0f;
        }
        __syncthreads();
        #pragma unroll
        for (int kk = 0; kk < 16; kk++) {
            float a[4], bv[4];
            #pragma unroll
            for (int i = 0; i < 4; i++) a[i] = As[kk][ty * 4 + i];
            const float4 w4 = *(const float4*)(&Ws[kk][tx * 4]);
            bv[0] = w4.x; bv[1] = w4.y; bv[2] = w4.z; bv[3] = w4.w;
            #pragma unroll
            for (int i = 0; i < 4; i++)
                #pragma unroll
                for (int j = 0; j < 4; j++)
                    acc[i][j] = fmaf(a[i], bv[j], acc[i][j]);
        }
        __syncthreads();
    }
    #pragma unroll
    for (int i = 0; i < 4; i++)
        #pragma unroll
        for (int j = 0; j < 4; j++)
            atomicAdd(&g_gmm[(size_t)(rowBase + ty * 4 + i) * 64 + tx * 4 + j], acc[i][j]);
}

__global__ __launch_bounds__(128)
void gmm_finish(const float* __restrict__ bg, float* __restrict__ out) {
    const int b = blockIdx.x * 128 + threadIdx.x;
    float gv[60];
    #pragma unroll
    for (int j = 0; j < 60; j++) gv[j] = g_gmm[(size_t)b * 64 + j] + bg[j];
    float e[M], s = 0.0f;
    #pragma unroll
    for (int j = 0; j < M; j++) {
        float ev = expf(gv[j]);
        ev = fminf(fmaxf(ev, 1e-10f), 1e10f);
        e[j] = ev; s += ev;
    }
    const float inv = 1.0f / s;
    float xp = 0.0f, yp = 0.0f;
    const size_t base = (size_t)b * OUT_ROW + U;
    #pragma unroll
    for (int j = 0; j < M; j++) {
        const float pi = e[j] * inv;
        out[base + j]         = pi;
        out[base + M + j]     = gv[M + j];
        out[base + 2 * M + j] = gv[2 * M + j];
        xp = fmaf(pi, gv[M + j], xp);
        yp = fmaf(pi, gv[2 * M + j], yp);
    }
    out[base + 3 * M]     = xp;
    out[base + 3 * M + 1] = yp;
    out[OUT_NS_OFF + (size_t)b * NS_ROW + U]     = xp;
    out[OUT_NS_OFF + (size_t)b * NS_ROW + U + 1] = yp;
}

// ---------------------------------------------------------------- launch
extern "C" void kernel_launch(void* const* d_in, const int* in_sizes, int n_in,
                              void* d_out, int out_size)
{
    const int*   inp      = (const int*)  d_in[0];
    const float* states   = (const float*)d_in[1];
    const float* bias_z   = (const float*)d_in[2];
    const float* R        = (const float*)d_in[3];
    const float* kernel_c = (const float*)d_in[4];
    const float* bias     = (const float*)d_in[5];
    const float* kernel_d = (const float*)d_in[6];
    const float* Wgmm     = (const float*)d_in[7];
    const float* bgmm     = (const float*)d_in[8];
    float* out = (float*)d_out;

    cudaFuncSetAttribute(stage_mma<1>, cudaFuncAttributeMaxDynamicSharedMemorySize, SMEM_BYTES);
    cudaFuncSetAttribute(stage_mma<2>, cudaFuncAttributeMaxDynamicSharedMemorySize, SMEM_BYTES);
    cudaFuncSetAttribute(stage_mma<3>, cudaFuncAttributeMaxDynamicSharedMemorySize, SMEM_BYTES);

    zero_gmm_kernel<<<256, 1024>>>();
    prep_B_kernel<<<dim3(128, 32), dim3(32, 8)>>>(R);
    prep_A1_kernel<<<BSZ * U / 256, 256>>>(states);

    dim3 blk(256);
    stage_mma<1><<<dim3(16, BSZ / BM), blk, SMEM_BYTES>>>(
        states, inp, kernel_c, bias_z, bias, kernel_d, out);
    stage_mma<2><<<dim3(8, BSZ / BM), blk, SMEM_BYTES>>>(
        states, inp, kernel_c, bias_z, bias, kernel_d, out);
    stage_mma<3><<<dim3(8, BSZ / BM), blk, SMEM_BYTES>>>(
        states, inp, kernel_c, bias_z, bias, kernel_d, out);

    gmm_partial<<<dim3(BSZ / 64, 8), blk>>>(out, Wgmm);
    gmm_finish<<<BSZ / 128, 128>>>(bgmm, out);
}

// round 5
// speedup vs baseline: 3.1064x; 1.3242x over previous
#include <cuda_runtime.h>
#include <cuda_fp16.h>
#include <math.h>
#include <stdint.h>

// ---------------------------------------------------------------- constants
#define BSZ 4096
#define U   1024
#define FOURU 4096
#define M   20
#define OUT_ROW 1086
#define NS_ROW  1026
#define OUT_NS_OFF (BSZ * OUT_ROW)
#define STATES_ROW 1026

// stage GEMM tiling
#define BM 128
#define BN 128
#define BK 32
#define NK (U / BK)                    // 32 k-iterations
#define ROWH 40                        // smem row stride in halves (32 + 8 pad)
#define ARR_BYTES (BM * ROWH * 2)      // 10240 B per tile array
#define STG_BYTES (3 * ARR_BYTES)      // Ahi, Alo, Bhi
#define NSTG 3
#define EPI_OFF (NSTG * STG_BYTES)     // 92160
#define SMEM_BYTES (EPI_OFF + 6 * 512)

// ---------------------------------------------------------------- scratch
__device__ __half g_Bh[4096u * 1024u];                 // R^T fp16, [n, k]
__device__ __half g_A1hi[BSZ * U], g_A1lo[BSZ * U];    // h split
__device__ __half g_A2hi[BSZ * U], g_A2lo[BSZ * U];    // r*h split
__device__ __half g_A3hi[BSZ * U], g_A3lo[BSZ * U];    // h_new split
__device__ float g_z[BSZ * U];
__device__ float g_gmm[BSZ * 64];

// ---------------------------------------------------------------- utils
__device__ __forceinline__ uint32_t smem_u32(const void* p) {
    uint32_t a;
    asm("{ .reg .u64 t; cvta.to.shared.u64 t, %1; cvt.u32.u64 %0, t; }"
        : "=r"(a) : "l"(p));
    return a;
}
#define CP_ASYNC16(dst, src) \
    asm volatile("cp.async.cg.shared.global [%0], [%1], 16;" :: "r"(dst), "l"(src))
#define CP_COMMIT() asm volatile("cp.async.commit_group;")
#define CP_WAIT(n)  asm volatile("cp.async.wait_group %0;" :: "n"(n))
#define LDSM_X4(r0, r1, r2, r3, addr) \
    asm volatile("ldmatrix.sync.aligned.m8n8.x4.shared.b16 {%0,%1,%2,%3}, [%4];" \
        : "=r"(r0), "=r"(r1), "=r"(r2), "=r"(r3) : "r"(addr))

__device__ __forceinline__ void mma16816(float* c, const uint32_t* a, const uint32_t* b) {
    asm volatile(
        "mma.sync.aligned.m16n8k16.row.col.f32.f16.f16.f32 "
        "{%0,%1,%2,%3}, {%4,%5,%6,%7}, {%8,%9}, {%0,%1,%2,%3};"
        : "+f"(c[0]), "+f"(c[1]), "+f"(c[2]), "+f"(c[3])
        : "r"(a[0]), "r"(a[1]), "r"(a[2]), "r"(a[3]), "r"(b[0]), "r"(b[1]));
}

__device__ __forceinline__ void halfsplit(float v, __half& hi, __half& lo) {
    hi = __float2half(v);
    lo = __float2half(v - __half2float(hi));
}

// ---------------------------------------------------------------- prep kernels
__global__ void zero_gmm_kernel() {
    g_gmm[blockIdx.x * 1024 + threadIdx.x] = 0.0f;
}

// Transpose R: [k,4096] fp32 -> g_Bh[n,1024] fp16
__global__ void prep_B_kernel(const float* __restrict__ R) {
    __shared__ float t[32][33];
    const int n0 = blockIdx.x * 32, k0 = blockIdx.y * 32;
    const int tx = threadIdx.x, ty = threadIdx.y;
    #pragma unroll
    for (int i = 0; i < 4; i++)
        t[ty + i * 8][tx] = R[(size_t)(k0 + ty + i * 8) * FOURU + n0 + tx];
    __syncthreads();
    #pragma unroll
    for (int i = 0; i < 4; i++) {
        const int n = n0 + ty + i * 8, k = k0 + tx;
        g_Bh[(size_t)n * U + k] = __float2half(t[tx][ty + i * 8]);
    }
}

// Split h (states[:, :U]) into g_A1
__global__ void prep_A1_kernel(const float* __restrict__ states) {
    const int idx = blockIdx.x * 256 + threadIdx.x;
    const int b = idx >> 10, k = idx & 1023;
    __half hi, lo;
    halfsplit(states[(size_t)b * STATES_ROW + k], hi, lo);
    g_A1hi[idx] = hi;
    g_A1lo[idx] = lo;
}

// ---------------------------------------------------------------- stage GEMM
// MODE 1: zr = h@R[:,0:2048]  (z for bx<8, r for bx>=8)
// MODE 2: hh = (r*h)@R[:,2048:3072] -> GRU blend, write h/new_state
// MODE 3: o  = h@R[:,3072:4096]     -> tanh, write out
template<int MODE>
__global__ __launch_bounds__(256, 2)
void stage_mma(const float* __restrict__ states,
               const int*   __restrict__ inp,
               const float* __restrict__ kernel_c,
               const float* __restrict__ bias_z,
               const float* __restrict__ bias,
               const float* __restrict__ kernel_d,
               float* __restrict__ out)
{
    extern __shared__ char smem[];
    const uint32_t sb = smem_u32(smem);

    const int tid  = threadIdx.x;
    const int wid  = tid >> 5;
    const int lane = tid & 31;
    const int wM   = wid >> 2;          // 0..1
    const int wN   = wid & 3;           // 0..3
    const int g    = lane >> 2;         // 0..7
    const int tig  = lane & 3;          // 0..3

    const int rowBase  = blockIdx.y * BM;
    const int bx       = blockIdx.x;
    const int stageOff = (MODE == 1) ? 0 : (MODE == 2 ? 2048 : 3072);
    const int nAbs     = stageOff + bx * BN;       // col base in 4096 pre-space

    const __half* Ah = (MODE == 1) ? g_A1hi : (MODE == 2 ? g_A2hi : g_A3hi);
    const __half* Al = (MODE == 1) ? g_A1lo : (MODE == 2 ? g_A2lo : g_A3lo);

    // epilogue smem
    int*   ch_s   = (int*)  (smem + EPI_OFF);
    float* d0_s   = (float*)(smem + EPI_OFF + 512);
    float* d1_s   = (float*)(smem + EPI_OFF + 1024);
    float* kd0_s  = (float*)(smem + EPI_OFF + 1536);
    float* kd1_s  = (float*)(smem + EPI_OFF + 2048);
    float* bias_s = (float*)(smem + EPI_OFF + 2560);
    for (int i = tid; i < BM; i += 256) {
        const int b = rowBase + i;
        ch_s[i] = inp[b];
        d0_s[i] = states[(size_t)b * STATES_ROW + U];
        d1_s[i] = states[(size_t)b * STATES_ROW + U + 1];
        kd0_s[i] = kernel_d[nAbs + i];
        kd1_s[i] = kernel_d[FOURU + nAbs + i];
        const int nsc = bx * BN + i;    // stage-local col
        float bv;
        if (MODE == 1) bv = (nsc < U) ? bias_z[nsc] : bias[nsc - U];
        else if (MODE == 2) bv = bias[U + nsc];
        else bv = bias[2 * U + nsc];
        bias_s[i] = bv;
    }

    // issue cp.async for one pipeline slot (3 arrays x 2 chunks/thread)
    auto issue = [&](int slot, int k0) {
        const uint32_t bbase = sb + slot * STG_BYTES;
        #pragma unroll
        for (int p = 0; p < 2; p++) {
            const int u = tid + p * 256;       // 0..511
            const int r = u >> 2, c = u & 3;
            const uint32_t d = r * 80 + c * 16;
            const size_t asrc = (size_t)(rowBase + r) * U + k0 + c * 8;
            const size_t bsrc = (size_t)(nAbs + r) * U + k0 + c * 8;
            CP_ASYNC16(bbase + d,                 (const void*)(Ah + asrc));
            CP_ASYNC16(bbase + ARR_BYTES + d,     (const void*)(Al + asrc));
            CP_ASYNC16(bbase + 2 * ARR_BYTES + d, (const void*)(g_Bh + bsrc));
        }
        CP_COMMIT();
    };

    float acc[4][4][4];
    #pragma unroll
    for (int i = 0; i < 4; i++)
        #pragma unroll
        for (int j = 0; j < 4; j++)
            #pragma unroll
            for (int q = 0; q < 4; q++) acc[i][j][q] = 0.0f;

    issue(0, 0);
    issue(1, BK);

    for (int kb = 0; kb < NK; kb++) {
        if (kb == NK - 1) { CP_WAIT(0); } else { CP_WAIT(1); }
        __syncthreads();
        if (kb + 2 < NK) issue((kb + 2) % NSTG, (kb + 2) * BK);

        const uint32_t bufA  = sb + (kb % NSTG) * STG_BYTES;
        const uint32_t bufAl = bufA + ARR_BYTES;
        const uint32_t bufB  = bufA + 2 * ARR_BYTES;

        #pragma unroll
        for (int s16 = 0; s16 < 2; s16++) {
            // B fragments: 2x ldmatrix.x4 covers 4 n-blocks of 8
            uint32_t bh[4][2];
            #pragma unroll
            for (int p = 0; p < 2; p++) {
                const int n  = wN * 32 + p * 16 + ((lane >> 4) << 3) + (lane & 7);
                const int kk = s16 * 16 + ((lane >> 3) & 1) * 8;
                LDSM_X4(bh[2 * p][0], bh[2 * p][1], bh[2 * p + 1][0], bh[2 * p + 1][1],
                        bufB + (n * ROWH + kk) * 2);
            }
            #pragma unroll
            for (int mf = 0; mf < 4; mf++) {
                const int row = wM * 64 + mf * 16 + (lane & 15);
                const int kk  = s16 * 16 + (lane >> 4) * 8;
                uint32_t ah[4], al[4];
                LDSM_X4(ah[0], ah[1], ah[2], ah[3], bufA  + (row * ROWH + kk) * 2);
                LDSM_X4(al[0], al[1], al[2], al[3], bufAl + (row * ROWH + kk) * 2);
                #pragma unroll
                for (int nf = 0; nf < 4; nf++) {
                    mma16816(acc[mf][nf], ah, bh[nf]);
                    mma16816(acc[mf][nf], al, bh[nf]);
                }
            }
        }
    }

    // ---------------- fused epilogue
    const bool zHalf = (MODE == 1) && (bx < 8);
    #pragma unroll
    for (int mf = 0; mf < 4; mf++) {
        #pragma unroll
        for (int hh = 0; hh < 2; hh++) {
            const int row = wM * 64 + mf * 16 + g + hh * 8;
            const int b   = rowBase + row;
            const int ch  = ch_s[row];
            const float d0 = d0_s[row], d1 = d1_s[row];
            #pragma unroll
            for (int nf = 0; nf < 4; nf++) {
                const int col = wN * 32 + nf * 8 + tig * 2;   // local col (even)
                const float2 kc = *(const float2*)(kernel_c + (size_t)ch * FOURU + nAbs + col);
                float v0 = acc[mf][nf][hh * 2]     + kc.x + d0 * kd0_s[col]     + d1 * kd1_s[col]     + bias_s[col];
                float v1 = acc[mf][nf][hh * 2 + 1] + kc.y + d0 * kd0_s[col + 1] + d1 * kd1_s[col + 1] + bias_s[col + 1];
                if (MODE == 1) {
                    const float s0 = 1.0f / (1.0f + expf(-v0));
                    const float s1 = 1.0f / (1.0f + expf(-v1));
                    if (zHalf) {
                        const int n = bx * BN + col;
                        *(float2*)&g_z[(size_t)b * U + n] = make_float2(s0, s1);
                    } else {
                        const int n2 = (bx - 8) * BN + col;
                        const float2 hv = *(const float2*)(states + (size_t)b * STATES_ROW + n2);
                        __half h0, l0, h1, l1;
                        halfsplit(s0 * hv.x, h0, l0);
                        halfsplit(s1 * hv.y, h1, l1);
                        *(__half2*)&g_A2hi[(size_t)b * U + n2] = __halves2half2(h0, h1);
                        *(__half2*)&g_A2lo[(size_t)b * U + n2] = __halves2half2(l0, l1);
                    }
                } else if (MODE == 2) {
                    const int n = bx * BN + col;
                    const float2 z2  = *(const float2*)&g_z[(size_t)b * U + n];
                    const float2 ho2 = *(const float2*)(states + (size_t)b * STATES_ROW + n);
                    const float hn0 = z2.x * ho2.x + (1.0f - z2.x) * tanhf(v0);
                    const float hn1 = z2.y * ho2.y + (1.0f - z2.y) * tanhf(v1);
                    *(float2*)&out[OUT_NS_OFF + (size_t)b * NS_ROW + n] = make_float2(hn0, hn1);
                    __half h0, l0, h1, l1;
                    halfsplit(hn0, h0, l0);
                    halfsplit(hn1, h1, l1);
                    *(__half2*)&g_A3hi[(size_t)b * U + n] = __halves2half2(h0, h1);
                    *(__half2*)&g_A3lo[(size_t)b * U + n] = __halves2half2(l0, l1);
                } else {
                    const int n = bx * BN + col;
                    *(float2*)&out[(size_t)b * OUT_ROW + n] = make_float2(tanhf(v0), tanhf(v1));
                }
            }
        }
    }
}

// ---------------------------------------------------------------- GMM head
__global__ __launch_bounds__(256)
void gmm_partial(const float* __restrict__ o_src,   // == out (o in first U cols)
                 const float* __restrict__ W)       // (1024, 60)
{
    __shared__ float As[16][68];
    __shared__ float Ws[16][64];
    const int tid = threadIdx.x;
    const int tx = tid & 15, ty = tid >> 4;
    const int rowBase = blockIdx.x * 64;
    const int kBase   = blockIdx.y * 128;

    float acc[4][4];
    #pragma unroll
    for (int i = 0; i < 4; i++)
        #pragma unroll
        for (int j = 0; j < 4; j++) acc[i][j] = 0.0f;

    for (int k0 = kBase; k0 < kBase + 128; k0 += 16) {
        #pragma unroll
        for (int i = 0; i < 4; i++) {
            const int idx = tid + i * 256;
            const int kk = idx & 15, r = idx >> 4;
            As[kk][r] = o_src[(size_t)(rowBase + r) * OUT_ROW + k0 + kk];
        }
        #pragma unroll
        for (int i = 0; i < 4; i++) {
            const int idx = tid + i * 256;
            const int c = idx & 63, kk = idx >> 6;
            Ws[kk][c] = (c < 60) ? W[(size_t)(k0 + kk) * 60 + c] : 0.0f;
        }
        __syncthreads();
        #pragma unroll
        for (int kk = 0; kk < 16; kk++) {
            float a[4], bv[4];
            #pragma unroll
            for (int i = 0; i < 4; i++) a[i] = As[kk][ty * 4 + i];
            const float4 w4 = *(const float4*)(&Ws[kk][tx * 4]);
            bv[0] = w4.x; bv[1] = w4.y; bv[2] = w4.z; bv[3] = w4.w;
            #pragma unroll
            for (int i = 0; i < 4; i++)
                #pragma unroll
                for (int j = 0; j < 4; j++)
                    acc[i][j] = fmaf(a[i], bv[j], acc[i][j]);
        }
        __syncthreads();
    }
    #pragma unroll
    for (int i = 0; i < 4; i++)
        #pragma unroll
        for (int j = 0; j < 4; j++)
            atomicAdd(&g_gmm[(size_t)(rowBase + ty * 4 + i) * 64 + tx * 4 + j], acc[i][j]);
}

__global__ __launch_bounds__(128)
void gmm_finish(const float* __restrict__ bg, float* __restrict__ out) {
    const int b = blockIdx.x * 128 + threadIdx.x;
    float gv[60];
    #pragma unroll
    for (int j = 0; j < 60; j++) gv[j] = g_gmm[(size_t)b * 64 + j] + bg[j];
    float e[M], s = 0.0f;
    #pragma unroll
    for (int j = 0; j < M; j++) {
        float ev = expf(gv[j]);
        ev = fminf(fmaxf(ev, 1e-10f), 1e10f);
        e[j] = ev; s += ev;
    }
    const float inv = 1.0f / s;
    float xp = 0.0f, yp = 0.0f;
    const size_t base = (size_t)b * OUT_ROW + U;
    #pragma unroll
    for (int j = 0; j < M; j++) {
        const float pi = e[j] * inv;
        out[base + j]         = pi;
        out[base + M + j]     = gv[M + j];
        out[base + 2 * M + j] = gv[2 * M + j];
        xp = fmaf(pi, gv[M + j], xp);
        yp = fmaf(pi, gv[2 * M + j], yp);
    }
    out[base + 3 * M]     = xp;
    out[base + 3 * M + 1] = yp;
    out[OUT_NS_OFF + (size_t)b * NS_ROW + U]     = xp;
    out[OUT_NS_OFF + (size_t)b * NS_ROW + U + 1] = yp;
}

// ---------------------------------------------------------------- launch
extern "C" void kernel_launch(void* const* d_in, const int* in_sizes, int n_in,
                              void* d_out, int out_size)
{
    const int*   inp      = (const int*)  d_in[0];
    const float* states   = (const float*)d_in[1];
    const float* bias_z   = (const float*)d_in[2];
    const float* R        = (const float*)d_in[3];
    const float* kernel_c = (const float*)d_in[4];
    const float* bias     = (const float*)d_in[5];
    const float* kernel_d = (const float*)d_in[6];
    const float* Wgmm     = (const float*)d_in[7];
    const float* bgmm     = (const float*)d_in[8];
    float* out = (float*)d_out;

    cudaFuncSetAttribute(stage_mma<1>, cudaFuncAttributeMaxDynamicSharedMemorySize, SMEM_BYTES);
    cudaFuncSetAttribute(stage_mma<2>, cudaFuncAttributeMaxDynamicSharedMemorySize, SMEM_BYTES);
    cudaFuncSetAttribute(stage_mma<3>, cudaFuncAttributeMaxDynamicSharedMemorySize, SMEM_BYTES);

    zero_gmm_kernel<<<256, 1024>>>();
    prep_B_kernel<<<dim3(128, 32), dim3(32, 8)>>>(R);
    prep_A1_kernel<<<BSZ * U / 256, 256>>>(states);

    dim3 blk(256);
    stage_mma<1><<<dim3(16, BSZ / BM), blk, SMEM_BYTES>>>(
        states, inp, kernel_c, bias_z, bias, kernel_d, out);
    stage_mma<2><<<dim3(8, BSZ / BM), blk, SMEM_BYTES>>>(
        states, inp, kernel_c, bias_z, bias, kernel_d, out);
    stage_mma<3><<<dim3(8, BSZ / BM), blk, SMEM_BYTES>>>(
        states, inp, kernel_c, bias_z, bias, kernel_d, out);

    gmm_partial<<<dim3(BSZ / 64, 8), blk>>>(out, Wgmm);
    gmm_finish<<<BSZ / 128, 128>>>(bgmm, out);
}

// round 6
// speedup vs baseline: 4.4529x; 1.4334x over previous
#include <cuda_runtime.h>
#include <cuda_fp16.h>
#include <math.h>
#include <stdint.h>

// ---------------------------------------------------------------- constants
#define BSZ 4096
#define U   1024
#define FOURU 4096
#define M   20
#define OUT_ROW 1086
#define NS_ROW  1026
#define OUT_NS_OFF (BSZ * OUT_ROW)
#define STATES_ROW 1026

// stage GEMM tiling
#define BM 128
#define BN 128
#define BK 32
#define NK (U / BK)                    // 32 k-iterations
#define ROWH 40                        // smem row stride in halves (32 + 8 pad)
#define ARR_BYTES (BM * ROWH * 2)      // 10240 B per tile array
#define STG_BYTES (2 * ARR_BYTES)      // A, B
#define NSTG 4
#define EPI_OFF (NSTG * STG_BYTES)     // 81920
#define SMEM_BYTES (EPI_OFF + 6 * 512)

// ---------------------------------------------------------------- scratch
__device__ __half g_Bh[4096u * 1024u];   // R^T fp16, [n, k]
__device__ __half g_A1[BSZ * U];         // h fp16
__device__ __half g_A2[BSZ * U];         // r*h fp16
__device__ __half g_A3[BSZ * U];         // h_new fp16
__device__ float g_z[BSZ * U];
__device__ float g_gmm[BSZ * 64];

// ---------------------------------------------------------------- utils
__device__ __forceinline__ uint32_t smem_u32(const void* p) {
    uint32_t a;
    asm("{ .reg .u64 t; cvta.to.shared.u64 t, %1; cvt.u32.u64 %0, t; }"
        : "=r"(a) : "l"(p));
    return a;
}
#define CP_ASYNC16(dst, src) \
    asm volatile("cp.async.cg.shared.global [%0], [%1], 16;" :: "r"(dst), "l"(src))
#define CP_COMMIT() asm volatile("cp.async.commit_group;")
#define CP_WAIT(n)  asm volatile("cp.async.wait_group %0;" :: "n"(n))
#define LDSM_X4(r0, r1, r2, r3, addr) \
    asm volatile("ldmatrix.sync.aligned.m8n8.x4.shared.b16 {%0,%1,%2,%3}, [%4];" \
        : "=r"(r0), "=r"(r1), "=r"(r2), "=r"(r3) : "r"(addr))

__device__ __forceinline__ void mma16816(float* c, const uint32_t* a, const uint32_t* b) {
    asm volatile(
        "mma.sync.aligned.m16n8k16.row.col.f32.f16.f16.f32 "
        "{%0,%1,%2,%3}, {%4,%5,%6,%7}, {%8,%9}, {%0,%1,%2,%3};"
        : "+f"(c[0]), "+f"(c[1]), "+f"(c[2]), "+f"(c[3])
        : "r"(a[0]), "r"(a[1]), "r"(a[2]), "r"(a[3]), "r"(b[0]), "r"(b[1]));
}

// ---------------------------------------------------------------- prep kernels
__global__ void zero_gmm_kernel() {
    g_gmm[blockIdx.x * 1024 + threadIdx.x] = 0.0f;
}

// Transpose R: [k,4096] fp32 -> g_Bh[n,1024] fp16
__global__ void prep_B_kernel(const float* __restrict__ R) {
    __shared__ float t[32][33];
    const int n0 = blockIdx.x * 32, k0 = blockIdx.y * 32;
    const int tx = threadIdx.x, ty = threadIdx.y;
    #pragma unroll
    for (int i = 0; i < 4; i++)
        t[ty + i * 8][tx] = R[(size_t)(k0 + ty + i * 8) * FOURU + n0 + tx];
    __syncthreads();
    #pragma unroll
    for (int i = 0; i < 4; i++) {
        const int n = n0 + ty + i * 8, k = k0 + tx;
        g_Bh[(size_t)n * U + k] = __float2half(t[tx][ty + i * 8]);
    }
}

// Convert h (states[:, :U]) to fp16
__global__ void prep_A1_kernel(const float* __restrict__ states) {
    const int idx = blockIdx.x * 256 + threadIdx.x;
    const int b = idx >> 10, k = idx & 1023;
    g_A1[idx] = __float2half(states[(size_t)b * STATES_ROW + k]);
}

// ---------------------------------------------------------------- stage GEMM
// MODE 1: zr = h@R[:,0:2048]  (z for bx<8, r for bx>=8)
// MODE 2: hh = (r*h)@R[:,2048:3072] -> GRU blend, write h/new_state
// MODE 3: o  = h@R[:,3072:4096]     -> tanh, write out
template<int MODE>
__global__ __launch_bounds__(256, 2)
void stage_mma(const float* __restrict__ states,
               const int*   __restrict__ inp,
               const float* __restrict__ kernel_c,
               const float* __restrict__ bias_z,
               const float* __restrict__ bias,
               const float* __restrict__ kernel_d,
               float* __restrict__ out)
{
    extern __shared__ char smem[];
    const uint32_t sb = smem_u32(smem);

    const int tid  = threadIdx.x;
    const int wid  = tid >> 5;
    const int lane = tid & 31;
    const int wM   = wid >> 2;          // 0..1
    const int wN   = wid & 3;           // 0..3
    const int g    = lane >> 2;         // 0..7
    const int tig  = lane & 3;          // 0..3

    const int rowBase  = blockIdx.y * BM;
    const int bx       = blockIdx.x;
    const int stageOff = (MODE == 1) ? 0 : (MODE == 2 ? 2048 : 3072);
    const int nAbs     = stageOff + bx * BN;       // col base in 4096 pre-space

    const __half* Ah = (MODE == 1) ? g_A1 : (MODE == 2 ? g_A2 : g_A3);

    // epilogue smem
    int*   ch_s   = (int*)  (smem + EPI_OFF);
    float* d0_s   = (float*)(smem + EPI_OFF + 512);
    float* d1_s   = (float*)(smem + EPI_OFF + 1024);
    float* kd0_s  = (float*)(smem + EPI_OFF + 1536);
    float* kd1_s  = (float*)(smem + EPI_OFF + 2048);
    float* bias_s = (float*)(smem + EPI_OFF + 2560);
    for (int i = tid; i < BM; i += 256) {
        const int b = rowBase + i;
        ch_s[i] = inp[b];
        d0_s[i] = states[(size_t)b * STATES_ROW + U];
        d1_s[i] = states[(size_t)b * STATES_ROW + U + 1];
        kd0_s[i] = kernel_d[nAbs + i];
        kd1_s[i] = kernel_d[FOURU + nAbs + i];
        const int nsc = bx * BN + i;    // stage-local col
        float bv;
        if (MODE == 1) bv = (nsc < U) ? bias_z[nsc] : bias[nsc - U];
        else if (MODE == 2) bv = bias[U + nsc];
        else bv = bias[2 * U + nsc];
        bias_s[i] = bv;
    }

    // issue cp.async for one pipeline slot (A + B, 2 chunks each per thread)
    auto issue = [&](int slot, int k0) {
        const uint32_t bbase = sb + slot * STG_BYTES;
        #pragma unroll
        for (int p = 0; p < 2; p++) {
            const int u = tid + p * 256;       // 0..511
            const int r = u >> 2, c = u & 3;
            const uint32_t d = r * 80 + c * 16;
            const size_t asrc = (size_t)(rowBase + r) * U + k0 + c * 8;
            const size_t bsrc = (size_t)(nAbs + r) * U + k0 + c * 8;
            CP_ASYNC16(bbase + d,             (const void*)(Ah + asrc));
            CP_ASYNC16(bbase + ARR_BYTES + d, (const void*)(g_Bh + bsrc));
        }
        CP_COMMIT();
    };

    float acc[4][4][4];
    #pragma unroll
    for (int i = 0; i < 4; i++)
        #pragma unroll
        for (int j = 0; j < 4; j++)
            #pragma unroll
            for (int q = 0; q < 4; q++) acc[i][j][q] = 0.0f;

    issue(0, 0);
    issue(1, BK);
    issue(2, 2 * BK);

    for (int kb = 0; kb < NK; kb++) {
        if (kb <= NK - 3)      { CP_WAIT(2); }
        else if (kb == NK - 2) { CP_WAIT(1); }
        else                   { CP_WAIT(0); }
        __syncthreads();
        if (kb + 3 < NK) issue((kb + 3) % NSTG, (kb + 3) * BK);

        const uint32_t bufA = sb + (kb % NSTG) * STG_BYTES;
        const uint32_t bufB = bufA + ARR_BYTES;

        #pragma unroll
        for (int s16 = 0; s16 < 2; s16++) {
            // B fragments: 2x ldmatrix.x4 covers 4 n-blocks of 8
            uint32_t bh[4][2];
            #pragma unroll
            for (int p = 0; p < 2; p++) {
                const int n  = wN * 32 + p * 16 + ((lane >> 4) << 3) + (lane & 7);
                const int kk = s16 * 16 + ((lane >> 3) & 1) * 8;
                LDSM_X4(bh[2 * p][0], bh[2 * p][1], bh[2 * p + 1][0], bh[2 * p + 1][1],
                        bufB + (n * ROWH + kk) * 2);
            }
            #pragma unroll
            for (int mf = 0; mf < 4; mf++) {
                const int row = wM * 64 + mf * 16 + (lane & 15);
                const int kk  = s16 * 16 + (lane >> 4) * 8;
                uint32_t ah[4];
                LDSM_X4(ah[0], ah[1], ah[2], ah[3], bufA + (row * ROWH + kk) * 2);
                #pragma unroll
                for (int nf = 0; nf < 4; nf++)
                    mma16816(acc[mf][nf], ah, bh[nf]);
            }
        }
    }

    // ---------------- fused epilogue
    const bool zHalf = (MODE == 1) && (bx < 8);
    #pragma unroll
    for (int mf = 0; mf < 4; mf++) {
        #pragma unroll
        for (int hh = 0; hh < 2; hh++) {
            const int row = wM * 64 + mf * 16 + g + hh * 8;
            const int b   = rowBase + row;
            const int ch  = ch_s[row];
            const float d0 = d0_s[row], d1 = d1_s[row];
            #pragma unroll
            for (int nf = 0; nf < 4; nf++) {
                const int col = wN * 32 + nf * 8 + tig * 2;   // local col (even)
                const float2 kc = *(const float2*)(kernel_c + (size_t)ch * FOURU + nAbs + col);
                float v0 = acc[mf][nf][hh * 2]     + kc.x + d0 * kd0_s[col]     + d1 * kd1_s[col]     + bias_s[col];
                float v1 = acc[mf][nf][hh * 2 + 1] + kc.y + d0 * kd0_s[col + 1] + d1 * kd1_s[col + 1] + bias_s[col + 1];
                if (MODE == 1) {
                    const float s0 = 1.0f / (1.0f + expf(-v0));
                    const float s1 = 1.0f / (1.0f + expf(-v1));
                    if (zHalf) {
                        const int n = bx * BN + col;
                        *(float2*)&g_z[(size_t)b * U + n] = make_float2(s0, s1);
                    } else {
                        const int n2 = (bx - 8) * BN + col;
                        const float2 hv = *(const float2*)(states + (size_t)b * STATES_ROW + n2);
                        *(__half2*)&g_A2[(size_t)b * U + n2] =
                            __halves2half2(__float2half(s0 * hv.x), __float2half(s1 * hv.y));
                    }
                } else if (MODE == 2) {
                    const int n = bx * BN + col;
                    const float2 z2  = *(const float2*)&g_z[(size_t)b * U + n];
                    const float2 ho2 = *(const float2*)(states + (size_t)b * STATES_ROW + n);
                    const float hn0 = z2.x * ho2.x + (1.0f - z2.x) * tanhf(v0);
                    const float hn1 = z2.y * ho2.y + (1.0f - z2.y) * tanhf(v1);
                    *(float2*)&out[OUT_NS_OFF + (size_t)b * NS_ROW + n] = make_float2(hn0, hn1);
                    *(__half2*)&g_A3[(size_t)b * U + n] =
                        __halves2half2(__float2half(hn0), __float2half(hn1));
                } else {
                    const int n = bx * BN + col;
                    *(float2*)&out[(size_t)b * OUT_ROW + n] = make_float2(tanhf(v0), tanhf(v1));
                }
            }
        }
    }
}

// ---------------------------------------------------------------- GMM head
__global__ __launch_bounds__(256)
void gmm_partial(const float* __restrict__ o_src,   // == out (o in first U cols)
                 const float* __restrict__ W)       // (1024, 60)
{
    __shared__ float As[16][68];
    __shared__ float Ws[16][64];
    const int tid = threadIdx.x;
    const int tx = tid & 15, ty = tid >> 4;
    const int rowBase = blockIdx.x * 64;
    const int kBase   = blockIdx.y * 128;

    float acc[4][4];
    #pragma unroll
    for (int i = 0; i < 4; i++)
        #pragma unroll
        for (int j = 0; j < 4; j++) acc[i][j] = 0.0f;

    for (int k0 = kBase; k0 < kBase + 128; k0 += 16) {
        #pragma unroll
        for (int i = 0; i < 4; i++) {
            const int idx = tid + i * 256;
            const int kk = idx & 15, r = idx >> 4;
            As[kk][r] = o_src[(size_t)(rowBase + r) * OUT_ROW + k0 + kk];
        }
        #pragma unroll
        for (int i = 0; i < 4; i++) {
            const int idx = tid + i * 256;
            const int c = idx & 63, kk = idx >> 6;
            Ws[kk][c] = (c < 60) ? W[(size_t)(k0 + kk) * 60 + c] : 0.0f;
        }
        __syncthreads();
        #pragma unroll
        for (int kk = 0; kk < 16; kk++) {
            float a[4], bv[4];
            #pragma unroll
            for (int i = 0; i < 4; i++) a[i] = As[kk][ty * 4 + i];
            const float4 w4 = *(const float4*)(&Ws[kk][tx * 4]);
            bv[0] = w4.x; bv[1] = w4.y; bv[2] = w4.z; bv[3] = w4.w;
            #pragma unroll
            for (int i = 0; i < 4; i++)
                #pragma unroll
                for (int j = 0; j < 4; j++)
                    acc[i][j] = fmaf(a[i], bv[j], acc[i][j]);
        }
        __syncthreads();
    }
    #pragma unroll
    for (int i = 0; i < 4; i++)
        #pragma unroll
        for (int j = 0; j < 4; j++)
            atomicAdd(&g_gmm[(size_t)(rowBase + ty * 4 + i) * 64 + tx * 4 + j], acc[i][j]);
}

__global__ __launch_bounds__(128)
void gmm_finish(const float* __restrict__ bg, float* __restrict__ out) {
    const int b = blockIdx.x * 128 + threadIdx.x;
    float gv[60];
    #pragma unroll
    for (int j = 0; j < 60; j++) gv[j] = g_gmm[(size_t)b * 64 + j] + bg[j];
    float e[M], s = 0.0f;
    #pragma unroll
    for (int j = 0; j < M; j++) {
        float ev = expf(gv[j]);
        ev = fminf(fmaxf(ev, 1e-10f), 1e10f);
        e[j] = ev; s += ev;
    }
    const float inv = 1.0f / s;
    float xp = 0.0f, yp = 0.0f;
    const size_t base = (size_t)b * OUT_ROW + U;
    #pragma unroll
    for (int j = 0; j < M; j++) {
        const float pi = e[j] * inv;
        out[base + j]         = pi;
        out[base + M + j]     = gv[M + j];
        out[base + 2 * M + j] = gv[2 * M + j];
        xp = fmaf(pi, gv[M + j], xp);
        yp = fmaf(pi, gv[2 * M + j], yp);
    }
    out[base + 3 * M]     = xp;
    out[base + 3 * M + 1] = yp;
    out[OUT_NS_OFF + (size_t)b * NS_ROW + U]     = xp;
    out[OUT_NS_OFF + (size_t)b * NS_ROW + U + 1] = yp;
}

// ---------------------------------------------------------------- launch
extern "C" void kernel_launch(void* const* d_in, const int* in_sizes, int n_in,
                              void* d_out, int out_size)
{
    const int*   inp      = (const int*)  d_in[0];
    const float* states   = (const float*)d_in[1];
    const float* bias_z   = (const float*)d_in[2];
    const float* R        = (const float*)d_in[3];
    const float* kernel_c = (const float*)d_in[4];
    const float* bias     = (const float*)d_in[5];
    const float* kernel_d = (const float*)d_in[6];
    const float* Wgmm     = (const float*)d_in[7];
    const float* bgmm     = (const float*)d_in[8];
    float* out = (float*)d_out;

    cudaFuncSetAttribute(stage_mma<1>, cudaFuncAttributeMaxDynamicSharedMemorySize, SMEM_BYTES);
    cudaFuncSetAttribute(stage_mma<2>, cudaFuncAttributeMaxDynamicSharedMemorySize, SMEM_BYTES);
    cudaFuncSetAttribute(stage_mma<3>, cudaFuncAttributeMaxDynamicSharedMemorySize, SMEM_BYTES);

    zero_gmm_kernel<<<256, 1024>>>();
    prep_B_kernel<<<dim3(128, 32), dim3(32, 8)>>>(R);
    prep_A1_kernel<<<BSZ * U / 256, 256>>>(states);

    dim3 blk(256);
    stage_mma<1><<<dim3(16, BSZ / BM), blk, SMEM_BYTES>>>(
        states, inp, kernel_c, bias_z, bias, kernel_d, out);
    stage_mma<2><<<dim3(8, BSZ / BM), blk, SMEM_BYTES>>>(
        states, inp, kernel_c, bias_z, bias, kernel_d, out);
    stage_mma<3><<<dim3(8, BSZ / BM), blk, SMEM_BYTES>>>(
        states, inp, kernel_c, bias_z, bias, kernel_d, out);

    gmm_partial<<<dim3(BSZ / 64, 8), blk>>>(out, Wgmm);
    gmm_finish<<<BSZ / 128, 128>>>(bgmm, out);
}

// round 7
// speedup vs baseline: 4.4960x; 1.0097x over previous
#include <cuda_runtime.h>
#include <cuda_fp16.h>
#include <math.h>
#include <stdint.h>

// ---------------------------------------------------------------- constants
#define BSZ 4096
#define U   1024
#define FOURU 4096
#define M   20
#define OUT_ROW 1086
#define NS_ROW  1026
#define OUT_NS_OFF (BSZ * OUT_ROW)
#define STATES_ROW 1026

// stage GEMM tiling
#define BM 128
#define BN 128
#define BK 32
#define NK (U / BK)                    // 32 k-iterations
#define NTHREADS 512
#define ROWH 40                        // smem row stride in halves (32 + 8 pad)
#define ARR_BYTES (BM * ROWH * 2)      // 10240 B per tile array
#define STG_BYTES (2 * ARR_BYTES)      // A, B
#define NSTG 4
#define EPI_OFF (NSTG * STG_BYTES)     // 81920
#define SMEM_BYTES (EPI_OFF + 6 * 512)

// ---------------------------------------------------------------- scratch
__device__ __half g_Bh[4096u * 1024u];   // R^T fp16, [n, k]
__device__ __half g_A1[BSZ * U];         // h fp16
__device__ __half g_A2[BSZ * U];         // r*h fp16
__device__ __half g_A3[BSZ * U];         // h_new fp16
__device__ float g_z[BSZ * U];
__device__ float g_gmm[BSZ * 64];

// ---------------------------------------------------------------- utils
__device__ __forceinline__ uint32_t smem_u32(const void* p) {
    uint32_t a;
    asm("{ .reg .u64 t; cvta.to.shared.u64 t, %1; cvt.u32.u64 %0, t; }"
        : "=r"(a) : "l"(p));
    return a;
}
#define CP_ASYNC16(dst, src) \
    asm volatile("cp.async.cg.shared.global [%0], [%1], 16;" :: "r"(dst), "l"(src))
#define CP_COMMIT() asm volatile("cp.async.commit_group;")
#define CP_WAIT(n)  asm volatile("cp.async.wait_group %0;" :: "n"(n))
#define LDSM_X4(r0, r1, r2, r3, addr) \
    asm volatile("ldmatrix.sync.aligned.m8n8.x4.shared.b16 {%0,%1,%2,%3}, [%4];" \
        : "=r"(r0), "=r"(r1), "=r"(r2), "=r"(r3) : "r"(addr))

__device__ __forceinline__ void mma16816(float* c, const uint32_t* a, const uint32_t* b) {
    asm volatile(
        "mma.sync.aligned.m16n8k16.row.col.f32.f16.f16.f32 "
        "{%0,%1,%2,%3}, {%4,%5,%6,%7}, {%8,%9}, {%0,%1,%2,%3};"
        : "+f"(c[0]), "+f"(c[1]), "+f"(c[2]), "+f"(c[3])
        : "r"(a[0]), "r"(a[1]), "r"(a[2]), "r"(a[3]), "r"(b[0]), "r"(b[1]));
}

// ---------------------------------------------------------------- prep kernels
__global__ void zero_gmm_kernel() {
    g_gmm[blockIdx.x * 1024 + threadIdx.x] = 0.0f;
}

// Transpose R: [k,4096] fp32 -> g_Bh[n,1024] fp16
__global__ void prep_B_kernel(const float* __restrict__ R) {
    __shared__ float t[32][33];
    const int n0 = blockIdx.x * 32, k0 = blockIdx.y * 32;
    const int tx = threadIdx.x, ty = threadIdx.y;
    #pragma unroll
    for (int i = 0; i < 4; i++)
        t[ty + i * 8][tx] = R[(size_t)(k0 + ty + i * 8) * FOURU + n0 + tx];
    __syncthreads();
    #pragma unroll
    for (int i = 0; i < 4; i++) {
        const int n = n0 + ty + i * 8, k = k0 + tx;
        g_Bh[(size_t)n * U + k] = __float2half(t[tx][ty + i * 8]);
    }
}

// Convert h (states[:, :U]) to fp16
__global__ void prep_A1_kernel(const float* __restrict__ states) {
    const int idx = blockIdx.x * 256 + threadIdx.x;
    const int b = idx >> 10, k = idx & 1023;
    g_A1[idx] = __float2half(states[(size_t)b * STATES_ROW + k]);
}

// ---------------------------------------------------------------- stage GEMM
// MODE 1: zr = h@R[:,0:2048]  (z for bx<8, r for bx>=8)
// MODE 2: hh = (r*h)@R[:,2048:3072] -> GRU blend, write h/new_state
// MODE 3: o  = h@R[:,3072:4096]     -> tanh, write out
// 512 threads, 16 warps in 4x4 grid, 32x32 warp tile.
template<int MODE>
__global__ __launch_bounds__(NTHREADS, 2)
void stage_mma(const float* __restrict__ states,
               const int*   __restrict__ inp,
               const float* __restrict__ kernel_c,
               const float* __restrict__ bias_z,
               const float* __restrict__ bias,
               const float* __restrict__ kernel_d,
               float* __restrict__ out)
{
    extern __shared__ char smem[];
    const uint32_t sb = smem_u32(smem);

    const int tid  = threadIdx.x;
    const int wid  = tid >> 5;
    const int lane = tid & 31;
    const int wM   = wid >> 2;          // 0..3
    const int wN   = wid & 3;           // 0..3
    const int g    = lane >> 2;         // 0..7
    const int tig  = lane & 3;          // 0..3

    const int rowBase  = blockIdx.y * BM;
    const int bx       = blockIdx.x;
    const int stageOff = (MODE == 1) ? 0 : (MODE == 2 ? 2048 : 3072);
    const int nAbs     = stageOff + bx * BN;       // col base in 4096 pre-space

    const __half* Ah = (MODE == 1) ? g_A1 : (MODE == 2 ? g_A2 : g_A3);

    // epilogue smem
    int*   ch_s   = (int*)  (smem + EPI_OFF);
    float* d0_s   = (float*)(smem + EPI_OFF + 512);
    float* d1_s   = (float*)(smem + EPI_OFF + 1024);
    float* kd0_s  = (float*)(smem + EPI_OFF + 1536);
    float* kd1_s  = (float*)(smem + EPI_OFF + 2048);
    float* bias_s = (float*)(smem + EPI_OFF + 2560);
    if (tid < BM) {
        const int i = tid;
        const int b = rowBase + i;
        ch_s[i] = inp[b];
        d0_s[i] = states[(size_t)b * STATES_ROW + U];
        d1_s[i] = states[(size_t)b * STATES_ROW + U + 1];
        kd0_s[i] = kernel_d[nAbs + i];
        kd1_s[i] = kernel_d[FOURU + nAbs + i];
        const int nsc = bx * BN + i;    // stage-local col
        float bv;
        if (MODE == 1) bv = (nsc < U) ? bias_z[nsc] : bias[nsc - U];
        else if (MODE == 2) bv = bias[U + nsc];
        else bv = bias[2 * U + nsc];
        bias_s[i] = bv;
    }

    // issue cp.async for one pipeline slot (A + B, 1 chunk each per thread)
    auto issue = [&](int slot, int k0) {
        const uint32_t bbase = sb + slot * STG_BYTES;
        const int r = tid >> 2, c = tid & 3;
        const uint32_t d = r * 80 + c * 16;
        const size_t asrc = (size_t)(rowBase + r) * U + k0 + c * 8;
        const size_t bsrc = (size_t)(nAbs + r) * U + k0 + c * 8;
        CP_ASYNC16(bbase + d,             (const void*)(Ah + asrc));
        CP_ASYNC16(bbase + ARR_BYTES + d, (const void*)(g_Bh + bsrc));
        CP_COMMIT();
    };

    float acc[2][4][4];
    #pragma unroll
    for (int i = 0; i < 2; i++)
        #pragma unroll
        for (int j = 0; j < 4; j++)
            #pragma unroll
            for (int q = 0; q < 4; q++) acc[i][j][q] = 0.0f;

    issue(0, 0);
    issue(1, BK);
    issue(2, 2 * BK);

    for (int kb = 0; kb < NK; kb++) {
        if (kb <= NK - 3)      { CP_WAIT(2); }
        else if (kb == NK - 2) { CP_WAIT(1); }
        else                   { CP_WAIT(0); }
        __syncthreads();
        if (kb + 3 < NK) issue((kb + 3) % NSTG, (kb + 3) * BK);

        const uint32_t bufA = sb + (kb % NSTG) * STG_BYTES;
        const uint32_t bufB = bufA + ARR_BYTES;

        #pragma unroll
        for (int s16 = 0; s16 < 2; s16++) {
            // B fragments: 2x ldmatrix.x4 covers 4 n-blocks of 8
            uint32_t bh[4][2];
            #pragma unroll
            for (int p = 0; p < 2; p++) {
                const int n  = wN * 32 + p * 16 + ((lane >> 4) << 3) + (lane & 7);
                const int kk = s16 * 16 + ((lane >> 3) & 1) * 8;
                LDSM_X4(bh[2 * p][0], bh[2 * p][1], bh[2 * p + 1][0], bh[2 * p + 1][1],
                        bufB + (n * ROWH + kk) * 2);
            }
            #pragma unroll
            for (int mf = 0; mf < 2; mf++) {
                const int row = wM * 32 + mf * 16 + (lane & 15);
                const int kk  = s16 * 16 + (lane >> 4) * 8;
                uint32_t ah[4];
                LDSM_X4(ah[0], ah[1], ah[2], ah[3], bufA + (row * ROWH + kk) * 2);
                #pragma unroll
                for (int nf = 0; nf < 4; nf++)
                    mma16816(acc[mf][nf], ah, bh[nf]);
            }
        }
    }

    // ---------------- fused epilogue
    const bool zHalf = (MODE == 1) && (bx < 8);
    #pragma unroll
    for (int mf = 0; mf < 2; mf++) {
        #pragma unroll
        for (int hh = 0; hh < 2; hh++) {
            const int row = wM * 32 + mf * 16 + g + hh * 8;
            const int b   = rowBase + row;
            const int ch  = ch_s[row];
            const float d0 = d0_s[row], d1 = d1_s[row];
            #pragma unroll
            for (int nf = 0; nf < 4; nf++) {
                const int col = wN * 32 + nf * 8 + tig * 2;   // local col (even)
                const float2 kc = *(const float2*)(kernel_c + (size_t)ch * FOURU + nAbs + col);
                float v0 = acc[mf][nf][hh * 2]     + kc.x + d0 * kd0_s[col]     + d1 * kd1_s[col]     + bias_s[col];
                float v1 = acc[mf][nf][hh * 2 + 1] + kc.y + d0 * kd0_s[col + 1] + d1 * kd1_s[col + 1] + bias_s[col + 1];
                if (MODE == 1) {
                    const float s0 = 1.0f / (1.0f + expf(-v0));
                    const float s1 = 1.0f / (1.0f + expf(-v1));
                    if (zHalf) {
                        const int n = bx * BN + col;
                        *(float2*)&g_z[(size_t)b * U + n] = make_float2(s0, s1);
                    } else {
                        const int n2 = (bx - 8) * BN + col;
                        const float2 hv = *(const float2*)(states + (size_t)b * STATES_ROW + n2);
                        *(__half2*)&g_A2[(size_t)b * U + n2] =
                            __halves2half2(__float2half(s0 * hv.x), __float2half(s1 * hv.y));
                    }
                } else if (MODE == 2) {
                    const int n = bx * BN + col;
                    const float2 z2  = *(const float2*)&g_z[(size_t)b * U + n];
                    const float2 ho2 = *(const float2*)(states + (size_t)b * STATES_ROW + n);
                    const float hn0 = z2.x * ho2.x + (1.0f - z2.x) * tanhf(v0);
                    const float hn1 = z2.y * ho2.y + (1.0f - z2.y) * tanhf(v1);
                    *(float2*)&out[OUT_NS_OFF + (size_t)b * NS_ROW + n] = make_float2(hn0, hn1);
                    *(__half2*)&g_A3[(size_t)b * U + n] =
                        __halves2half2(__float2half(hn0), __float2half(hn1));
                } else {
                    const int n = bx * BN + col;
                    *(float2*)&out[(size_t)b * OUT_ROW + n] = make_float2(tanhf(v0), tanhf(v1));
                }
            }
        }
    }
}

// ---------------------------------------------------------------- GMM head
__global__ __launch_bounds__(256)
void gmm_partial(const float* __restrict__ o_src,   // == out (o in first U cols)
                 const float* __restrict__ W)       // (1024, 60)
{
    __shared__ float As[16][68];
    __shared__ float Ws[16][64];
    const int tid = threadIdx.x;
    const int tx = tid & 15, ty = tid >> 4;
    const int rowBase = blockIdx.x * 64;
    const int kBase   = blockIdx.y * 128;

    float acc[4][4];
    #pragma unroll
    for (int i = 0; i < 4; i++)
        #pragma unroll
        for (int j = 0; j < 4; j++) acc[i][j] = 0.0f;

    for (int k0 = kBase; k0 < kBase + 128; k0 += 16) {
        #pragma unroll
        for (int i = 0; i < 4; i++) {
            const int idx = tid + i * 256;
            const int kk = idx & 15, r = idx >> 4;
            As[kk][r] = o_src[(size_t)(rowBase + r) * OUT_ROW + k0 + kk];
        }
        #pragma unroll
        for (int i = 0; i < 4; i++) {
            const int idx = tid + i * 256;
            const int c = idx & 63, kk = idx >> 6;
            Ws[kk][c] = (c < 60) ? W[(size_t)(k0 + kk) * 60 + c] : 0.0f;
        }
        __syncthreads();
        #pragma unroll
        for (int kk = 0; kk < 16; kk++) {
            float a[4], bv[4];
            #pragma unroll
            for (int i = 0; i < 4; i++) a[i] = As[kk][ty * 4 + i];
            const float4 w4 = *(const float4*)(&Ws[kk][tx * 4]);
            bv[0] = w4.x; bv[1] = w4.y; bv[2] = w4.z; bv[3] = w4.w;
            #pragma unroll
            for (int i = 0; i < 4; i++)
                #pragma unroll
                for (int j = 0; j < 4; j++)
                    acc[i][j] = fmaf(a[i], bv[j], acc[i][j]);
        }
        __syncthreads();
    }
    #pragma unroll
    for (int i = 0; i < 4; i++)
        #pragma unroll
        for (int j = 0; j < 4; j++)
            atomicAdd(&g_gmm[(size_t)(rowBase + ty * 4 + i) * 64 + tx * 4 + j], acc[i][j]);
}

__global__ __launch_bounds__(128)
void gmm_finish(const float* __restrict__ bg, float* __restrict__ out) {
    const int b = blockIdx.x * 128 + threadIdx.x;
    float gv[60];
    #pragma unroll
    for (int j = 0; j < 60; j++) gv[j] = g_gmm[(size_t)b * 64 + j] + bg[j];
    float e[M], s = 0.0f;
    #pragma unroll
    for (int j = 0; j < M; j++) {
        float ev = expf(gv[j]);
        ev = fminf(fmaxf(ev, 1e-10f), 1e10f);
        e[j] = ev; s += ev;
    }
    const float inv = 1.0f / s;
    float xp = 0.0f, yp = 0.0f;
    const size_t base = (size_t)b * OUT_ROW + U;
    #pragma unroll
    for (int j = 0; j < M; j++) {
        const float pi = e[j] * inv;
        out[base + j]         = pi;
        out[base + M + j]     = gv[M + j];
        out[base + 2 * M + j] = gv[2 * M + j];
        xp = fmaf(pi, gv[M + j], xp);
        yp = fmaf(pi, gv[2 * M + j], yp);
    }
    out[base + 3 * M]     = xp;
    out[base + 3 * M + 1] = yp;
    out[OUT_NS_OFF + (size_t)b * NS_ROW + U]     = xp;
    out[OUT_NS_OFF + (size_t)b * NS_ROW + U + 1] = yp;
}

// ---------------------------------------------------------------- launch
extern "C" void kernel_launch(void* const* d_in, const int* in_sizes, int n_in,
                              void* d_out, int out_size)
{
    const int*   inp      = (const int*)  d_in[0];
    const float* states   = (const float*)d_in[1];
    const float* bias_z   = (const float*)d_in[2];
    const float* R        = (const float*)d_in[3];
    const float* kernel_c = (const float*)d_in[4];
    const float* bias     = (const float*)d_in[5];
    const float* kernel_d = (const float*)d_in[6];
    const float* Wgmm     = (const float*)d_in[7];
    const float* bgmm     = (const float*)d_in[8];
    float* out = (float*)d_out;

    cudaFuncSetAttribute(stage_mma<1>, cudaFuncAttributeMaxDynamicSharedMemorySize, SMEM_BYTES);
    cudaFuncSetAttribute(stage_mma<2>, cudaFuncAttributeMaxDynamicSharedMemorySize, SMEM_BYTES);
    cudaFuncSetAttribute(stage_mma<3>, cudaFuncAttributeMaxDynamicSharedMemorySize, SMEM_BYTES);

    zero_gmm_kernel<<<256, 1024>>>();
    prep_B_kernel<<<dim3(128, 32), dim3(32, 8)>>>(R);
    prep_A1_kernel<<<BSZ * U / 256, 256>>>(states);

    dim3 blk(NTHREADS);
    stage_mma<1><<<dim3(16, BSZ / BM), blk, SMEM_BYTES>>>(
        states, inp, kernel_c, bias_z, bias, kernel_d, out);
    stage_mma<2><<<dim3(8, BSZ / BM), blk, SMEM_BYTES>>>(
        states, inp, kernel_c, bias_z, bias, kernel_d, out);
    stage_mma<3><<<dim3(8, BSZ / BM), blk, SMEM_BYTES>>>(
        states, inp, kernel_c, bias_z, bias, kernel_d, out);

    gmm_partial<<<dim3(BSZ / 64, 8), dim3(256)>>>(out, Wgmm);
    gmm_finish<<<BSZ / 128, 128>>>(bgmm, out);
}